// round 12
// baseline (speedup 1.0000x reference)
#include <cuda_runtime.h>
#include <cuda_bf16.h>
#include <cstdint>

#define NLEAF 4096
#define NNODE 8191
#define NROW  8192
#define HID   512

#define OFF_EF     16382
#define OFF_EMB    16807932
#define OFF_FOCAL  21002236

// ----------------------------- scratch ---------------------------------------
__device__ float g_dW[NROW*HID];
__device__ float g_h[NROW*HID];
__device__ float g_cvec[HID];
__device__ float g_hf[HID];
__device__ float g_c[NNODE];          // leaves stay 0 forever
__device__ int   g_postF[NNODE];
__device__ int   g_preF[NNODE];

// bf16 split operand buffers (k-contiguous)
__device__ __nv_bfloat16 gA_hi[(size_t)NROW*1024];
__device__ __nv_bfloat16 gA_lo[(size_t)NROW*1024];
__device__ __nv_bfloat16 gZ_hi[(size_t)NROW*512];
__device__ __nv_bfloat16 gZ_lo[(size_t)NROW*512];
__device__ __nv_bfloat16 gB0_hi[(size_t)512*1024];   // W2   [n][k]
__device__ __nv_bfloat16 gB0_lo[(size_t)512*1024];
__device__ __nv_bfloat16 gB1_hi[(size_t)512*1024];   // Bm   [n][k]
__device__ __nv_bfloat16 gB1_lo[(size_t)512*1024];
__device__ __nv_bfloat16 gB2_hi[(size_t)512*1024];   // Wh2  [n][k]
__device__ __nv_bfloat16 gB2_lo[(size_t)512*1024];

// ----------------------------- helpers ----------------------------------------
__device__ __forceinline__ void st_rel(int* p, int v) {
    asm volatile("st.release.gpu.global.b32 [%0], %1;" :: "l"(p), "r"(v) : "memory");
}
__device__ __forceinline__ int ld_acq(const int* p) {
    int v;
    asm volatile("ld.acquire.gpu.global.b32 %0, [%1];" : "=r"(v) : "l"(p) : "memory");
    return v;
}
__device__ __forceinline__ void split_bf(float v, __nv_bfloat16 &h, __nv_bfloat16 &l) {
    h = __float2bfloat16(v);
    l = __float2bfloat16(v - __bfloat162float(h));
}
__device__ __forceinline__ float eluf(float x) { return x > 0.f ? x : expm1f(x); }

__device__ __forceinline__ void mma_bf16(float* d, const uint32_t* a, uint32_t b0, uint32_t b1) {
    asm volatile(
        "mma.sync.aligned.m16n8k16.row.col.f32.bf16.bf16.f32 "
        "{%0,%1,%2,%3}, {%4,%5,%6,%7}, {%8,%9}, {%0,%1,%2,%3};"
        : "+f"(d[0]), "+f"(d[1]), "+f"(d[2]), "+f"(d[3])
        : "r"(a[0]), "r"(a[1]), "r"(a[2]), "r"(a[3]), "r"(b0), "r"(b1));
}

// ----------------------------- launch 1: prep ---------------------------------
__global__ void k_prep(const float* __restrict__ W2, const float* __restrict__ Wh2,
                       const int* __restrict__ ns, const int* __restrict__ focal,
                       const float* __restrict__ W1, const float* __restrict__ bh3,
                       float* __restrict__ out) {
    int b = blockIdx.x;
    if (b < 1024) {
        if (b < 64) {
            int i = b*256 + threadIdx.x;    // covers 16384 >= 2*NNODE
            if (i < NNODE) { g_postF[i] = 0; out[i] = bh3[0]; }
            else if (i < 2*NNODE) g_preF[i - NNODE] = 0;
        }
        const float* W = (b < 512) ? W2 : Wh2;
        __nv_bfloat16* bh = (b < 512) ? gB0_hi : gB2_hi;
        __nv_bfloat16* bl = (b < 512) ? gB0_lo : gB2_lo;
        int n = b & 511;
        for (int k = threadIdx.x; k < 512; k += blockDim.x) {
            float v = W[(size_t)k*512 + n];
            __nv_bfloat16 h, l; split_bf(v, h, l);
            bh[(size_t)n*1024 + k] = h;
            bl[(size_t)n*1024 + k] = l;
        }
        return;
    }
    int bb = b - 1024;                      // 0..4096
    int u, src;
    if (bb == NLEAF) { u = NNODE; src = focal[0]; }
    else {
        u = bb; src = ns[bb];
        if (threadIdx.x == 0) out[OFF_FOCAL + bb] = (bb == focal[0]) ? 1.f : 0.f;
        if (src < 0) return;
    }
    if (threadIdx.x < 128) {
        const float4* w = (const float4*)(W1 + (size_t)src*HID);
        float4* d = (float4*)(g_dW + (size_t)u*HID);
        d[threadIdx.x] = w[threadIdx.x];
    }
}

// ----------------------------- launch 2: tree + agg phase 0 -------------------
// 512 blocks x 256 threads = 4096 warps. Warp w (< 4095) computes internal node
// NLEAF+w (postorder then preorder, flag-chased). Then EVERY warp aggregates
// rows 2w, 2w+1 of g_dW into g_h (GCN hop 1 + relu + bias), waiting on the
// preF flags of the row and its internal neighbors.
__global__ void k_tree(const int* __restrict__ ch0, const int* __restrict__ ch1,
                       const int* __restrict__ parent, const int* __restrict__ neigh,
                       const float* __restrict__ bias) {
    const int w    = blockIdx.x * (blockDim.x >> 5) + (threadIdx.x >> 5);
    const int lane = threadIdx.x & 31;
    const int NI   = NNODE - NLEAF;
    const int root = NNODE - 1;

    if (w < NI) {
        const int u = NLEAF + w;
        const int a = ch0[u], b = ch1[u];

        if (a >= NLEAF) while (!ld_acq(&g_postF[a])) { }
        if (b >= NLEAF) while (!ld_acq(&g_postF[b])) { }
        __syncwarp();
        float ca = __ldcg(&g_c[a]);
        float cb = __ldcg(&g_c[b]);
        float cu = 1.f / (3.f - ca - cb);
        const float4* pa = (const float4*)(g_dW + (size_t)a*HID);
        const float4* pb = (const float4*)(g_dW + (size_t)b*HID);
        float4*       pu = (float4*)(g_dW + (size_t)u*HID);
        #pragma unroll
        for (int j = 0; j < 4; j++) {
            int c4 = lane + j*32;
            float4 x = __ldcg(pa + c4), y = __ldcg(pb + c4), r;
            r.x = cu*(x.x+y.x); r.y = cu*(x.y+y.y);
            r.z = cu*(x.z+y.z); r.w = cu*(x.w+y.w);
            pu[c4] = r;
        }
        if (lane == 0) g_c[u] = cu;
        __threadfence();
        __syncwarp();
        if (lane == 0) {
            st_rel(&g_postF[u], 1);
            if (u == root) st_rel(&g_preF[u], 1);
        }
        __syncwarp();

        if (u != root) {
            const int p = parent[u];
            while (!ld_acq(&g_preF[p])) { }
            __syncwarp();
            const float4* pp = (const float4*)(g_dW + (size_t)p*HID);
            #pragma unroll
            for (int j = 0; j < 4; j++) {
                int c4 = lane + j*32;
                float4 x = __ldcg(pp + c4);
                float4 r = pu[c4];
                r.x += cu*x.x; r.y += cu*x.y; r.z += cu*x.z; r.w += cu*x.w;
                pu[c4] = r;
            }
            __threadfence();
            __syncwarp();
            if (lane == 0) st_rel(&g_preF[u], 1);
            __syncwarp();
        }
    }

    // ---- agg phase 0: rows 2w, 2w+1 ----
    #pragma unroll
    for (int q = 0; q < 2; q++) {
        int rrow = 2*w + q;                 // 0..8191
        int n0 = neigh[3*rrow], n1 = neigh[3*rrow+1], n2 = neigh[3*rrow+2];
        if (lane == 0) {
            if (rrow >= NLEAF && rrow < NNODE) while (!ld_acq(&g_preF[rrow])) { }
            if (n0 >= NLEAF && n0 < NNODE)     while (!ld_acq(&g_preF[n0])) { }
            if (n1 >= NLEAF && n1 < NNODE)     while (!ld_acq(&g_preF[n1])) { }
            if (n2 >= NLEAF && n2 < NNODE)     while (!ld_acq(&g_preF[n2])) { }
        }
        __syncwarp();
        float inv = 1.f / (1.f + (n0 >= 0) + (n1 >= 0) + (n2 >= 0));
        const float4* s  = (const float4*)(g_dW + (size_t)rrow*HID);
        const float4* p0 = (const float4*)(g_dW + (size_t)(n0 >= 0 ? n0 : 0)*HID);
        const float4* p1 = (const float4*)(g_dW + (size_t)(n1 >= 0 ? n1 : 0)*HID);
        const float4* p2 = (const float4*)(g_dW + (size_t)(n2 >= 0 ? n2 : 0)*HID);
        float4* dst = (float4*)(g_h + (size_t)rrow*HID);
        const float4* bb4 = (const float4*)bias;
        #pragma unroll
        for (int j4 = 0; j4 < 4; j4++) {
            int j = lane + j4*32;
            float4 v = __ldcg(s + j);
            if (n0 >= 0) { float4 t = __ldcg(p0 + j); v.x += t.x; v.y += t.y; v.z += t.z; v.w += t.w; }
            if (n1 >= 0) { float4 t = __ldcg(p1 + j); v.x += t.x; v.y += t.y; v.z += t.z; v.w += t.w; }
            if (n2 >= 0) { float4 t = __ldcg(p2 + j); v.x += t.x; v.y += t.y; v.z += t.z; v.w += t.w; }
            float4 bv = bb4[j];
            v.x = fmaxf(v.x*inv + bv.x, 0.f); v.y = fmaxf(v.y*inv + bv.y, 0.f);
            v.z = fmaxf(v.z*inv + bv.z, 0.f); v.w = fmaxf(v.w*inv + bv.w, 0.f);
            dst[j] = v;
        }
    }
}

// ----------------------------- launch 3: agg phase 1 + split ------------------
__global__ void k_agg(const int* __restrict__ neigh) {
    int u = blockIdx.x;
    int n0 = neigh[3*u], n1 = neigh[3*u+1], n2 = neigh[3*u+2];
    float inv = 1.f / (1.f + (n0 >= 0) + (n1 >= 0) + (n2 >= 0));
    const float4* s  = (const float4*)(g_h + (size_t)u*HID);
    const float4* p0 = (const float4*)(g_h + (size_t)(n0 >= 0 ? n0 : 0)*HID);
    const float4* p1 = (const float4*)(g_h + (size_t)(n1 >= 0 ? n1 : 0)*HID);
    const float4* p2 = (const float4*)(g_h + (size_t)(n2 >= 0 ? n2 : 0)*HID);
    int j = threadIdx.x;
    float4 v = s[j];
    if (n0 >= 0) { float4 t = p0[j]; v.x += t.x; v.y += t.y; v.z += t.z; v.w += t.w; }
    if (n1 >= 0) { float4 t = p1[j]; v.x += t.x; v.y += t.y; v.z += t.z; v.w += t.w; }
    if (n2 >= 0) { float4 t = p2[j]; v.x += t.x; v.y += t.y; v.z += t.z; v.w += t.w; }
    v.x *= inv; v.y *= inv; v.z *= inv; v.w *= inv;
    __nv_bfloat16 h0,l0,h1,l1,h2,l2,h3,l3;
    split_bf(v.x, h0, l0); split_bf(v.y, h1, l1);
    split_bf(v.z, h2, l2); split_bf(v.w, h3, l3);
    ushort4 sh = { __bfloat16_as_ushort(h0), __bfloat16_as_ushort(h1),
                   __bfloat16_as_ushort(h2), __bfloat16_as_ushort(h3) };
    ushort4 sl = { __bfloat16_as_ushort(l0), __bfloat16_as_ushort(l1),
                   __bfloat16_as_ushort(l2), __bfloat16_as_ushort(l3) };
    *(ushort4*)(gA_hi + (size_t)u*1024 + 4*j) = sh;
    *(ushort4*)(gA_lo + (size_t)u*1024 + 4*j) = sl;
}

// ----------------------------- mma.sync bf16x3 GEMM ---------------------------
// mode 0: A=gA (stride 1024), B=gB0, K=512 ; Cout = D + bias (fp32)
// mode 1: A=gA (stride 1024), B=gB1, K=1024; gZ = split(elu(D + cvec + t*wt + r*wr))
// mode 2: A=gZ (stride 512),  B=gB2, K=512 ; z=elu(D+bias); atomicAdd(out[m], z*W3[n]) (wt=W3)
#define SROW 40   // smem row stride in bf16 (80B)
__global__ __launch_bounds__(256, 2) void k_mma(
        int mode, int M, int K,
        const float* __restrict__ bias,
        const float* __restrict__ wt, const float* __restrict__ wr,
        const float* __restrict__ tv, const float* __restrict__ rv,
        float* __restrict__ Cout) {
    const __nv_bfloat16* Ahi = (mode == 2) ? gZ_hi : gA_hi;
    const __nv_bfloat16* Alo = (mode == 2) ? gZ_lo : gA_lo;
    const __nv_bfloat16* Bhi = (mode == 0) ? gB0_hi : (mode == 1 ? gB1_hi : gB2_hi);
    const __nv_bfloat16* Blo = (mode == 0) ? gB0_lo : (mode == 1 ? gB1_lo : gB2_lo);
    const int strideA = (mode == 2) ? 512 : 1024;

    __shared__ __align__(16) __nv_bfloat16 sm[4*128*SROW];   // 40960 B: Ah, Al, Bh, Bl
    const int tid  = threadIdx.x;
    const int wid  = tid >> 5;
    const int lane = tid & 31;
    const int gid  = lane >> 2;       // 0..7
    const int tig  = lane & 3;        // 0..3
    const int m0 = blockIdx.y * 128;
    const int n0 = blockIdx.x * 128;
    const int wm = (wid & 3) * 32;    // warp m offset
    const int wn = (wid >> 2) * 64;   // warp n offset
    const int Cn = K >> 5;            // 32-wide K chunks

    float acc[2][8][4];
    #pragma unroll
    for (int i = 0; i < 2; i++)
        #pragma unroll
        for (int j = 0; j < 8; j++)
            #pragma unroll
            for (int q = 0; q < 4; q++) acc[i][j][q] = 0.f;

    uint4 rAh[2], rAl[2], rBh[2], rBl[2];
    auto load_g = [&](int c) {
        const size_t kb = (size_t)c * 32;
        #pragma unroll
        for (int it = 0; it < 2; it++) {
            int idx = it*256 + tid;
            int row = idx >> 2, seg = idx & 3;
            rAh[it] = *(const uint4*)(Ahi + (size_t)(m0+row)*strideA + kb + seg*8);
            rAl[it] = *(const uint4*)(Alo + (size_t)(m0+row)*strideA + kb + seg*8);
            rBh[it] = *(const uint4*)(Bhi + (size_t)(n0+row)*1024 + kb + seg*8);
            rBl[it] = *(const uint4*)(Blo + (size_t)(n0+row)*1024 + kb + seg*8);
        }
    };
    auto store_s = [&]() {
        #pragma unroll
        for (int it = 0; it < 2; it++) {
            int idx = it*256 + tid;
            int row = idx >> 2, seg = idx & 3;
            int so = row*SROW + seg*8;
            *(uint4*)(sm + 0*128*SROW + so) = rAh[it];
            *(uint4*)(sm + 1*128*SROW + so) = rAl[it];
            *(uint4*)(sm + 2*128*SROW + so) = rBh[it];
            *(uint4*)(sm + 3*128*SROW + so) = rBl[it];
        }
    };

    load_g(0);
    for (int c = 0; c < Cn; c++) {
        store_s();
        __syncthreads();
        if (c + 1 < Cn) load_g(c + 1);     // global->reg prefetch overlaps compute
        const __nv_bfloat16* sAh = sm;
        const __nv_bfloat16* sAl = sm + 128*SROW;
        const __nv_bfloat16* sBh = sm + 2*128*SROW;
        const __nv_bfloat16* sBl = sm + 3*128*SROW;
        #pragma unroll
        for (int ks = 0; ks < 32; ks += 16) {
            uint32_t aH[2][4], aL[2][4];
            #pragma unroll
            for (int i = 0; i < 2; i++) {
                int rb = wm + i*16 + gid;
                int cb = ks + tig*2;
                aH[i][0] = *(const uint32_t*)(sAh + rb*SROW + cb);
                aH[i][1] = *(const uint32_t*)(sAh + (rb+8)*SROW + cb);
                aH[i][2] = *(const uint32_t*)(sAh + rb*SROW + cb + 8);
                aH[i][3] = *(const uint32_t*)(sAh + (rb+8)*SROW + cb + 8);
                aL[i][0] = *(const uint32_t*)(sAl + rb*SROW + cb);
                aL[i][1] = *(const uint32_t*)(sAl + (rb+8)*SROW + cb);
                aL[i][2] = *(const uint32_t*)(sAl + rb*SROW + cb + 8);
                aL[i][3] = *(const uint32_t*)(sAl + (rb+8)*SROW + cb + 8);
            }
            #pragma unroll
            for (int j = 0; j < 8; j++) {
                int nb = wn + j*8 + gid;
                int cb = ks + tig*2;
                uint32_t bh0 = *(const uint32_t*)(sBh + nb*SROW + cb);
                uint32_t bh1 = *(const uint32_t*)(sBh + nb*SROW + cb + 8);
                uint32_t bl0 = *(const uint32_t*)(sBl + nb*SROW + cb);
                uint32_t bl1 = *(const uint32_t*)(sBl + nb*SROW + cb + 8);
                #pragma unroll
                for (int i = 0; i < 2; i++) {
                    mma_bf16(acc[i][j], aH[i], bh0, bh1);
                    mma_bf16(acc[i][j], aH[i], bl0, bl1);
                    mma_bf16(acc[i][j], aL[i], bh0, bh1);
                }
            }
        }
        __syncthreads();
    }

    // ----- epilogue -----
    #pragma unroll
    for (int i = 0; i < 2; i++) {
        #pragma unroll
        for (int r2 = 0; r2 < 2; r2++) {
            int m = m0 + wm + i*16 + gid + r2*8;
            if (m >= M) continue;
            float t = 0.f, r = 0.f;
            if (mode == 1) { t = tv[m]; r = rv[m]; }
            float part = 0.f;                 // mode 2: logits partial
            #pragma unroll
            for (int j = 0; j < 8; j++) {
                int n = n0 + wn + j*8 + tig*2;
                float v0 = acc[i][j][r2*2 + 0];
                float v1 = acc[i][j][r2*2 + 1];
                if (mode == 0) {
                    float2 bv = *(const float2*)&bias[n];
                    *(float2*)(Cout + (size_t)m*512 + n) = make_float2(v0 + bv.x, v1 + bv.y);
                } else if (mode == 1) {
                    float2 cv = *(const float2*)&g_cvec[n];
                    float2 wtv = *(const float2*)&wt[n];
                    float2 wrv = *(const float2*)&wr[n];
                    float z0 = eluf(v0 + cv.x + t*wtv.x + r*wrv.x);
                    float z1 = eluf(v1 + cv.y + t*wtv.y + r*wrv.y);
                    __nv_bfloat16 h0, l0, h1, l1;
                    split_bf(z0, h0, l0); split_bf(z1, h1, l1);
                    ushort2 sh = { __bfloat16_as_ushort(h0), __bfloat16_as_ushort(h1) };
                    ushort2 sl = { __bfloat16_as_ushort(l0), __bfloat16_as_ushort(l1) };
                    *(ushort2*)(gZ_hi + (size_t)m*512 + n) = sh;
                    *(ushort2*)(gZ_lo + (size_t)m*512 + n) = sl;
                } else {
                    float2 bv = *(const float2*)&bias[n];
                    float2 w3 = *(const float2*)&wt[n];     // wt = W_h3
                    part += eluf(v0 + bv.x)*w3.x + eluf(v1 + bv.y)*w3.y;
                }
            }
            if (mode == 2) {
                part += __shfl_xor_sync(0xffffffffu, part, 1);
                part += __shfl_xor_sync(0xffffffffu, part, 2);
                if (tig == 0) atomicAdd(&Cout[m], part);
            }
        }
    }
}

// ----------------------------- launch 5: hf + cvec (parallel) -----------------
__global__ void k_hfcvec(const float* __restrict__ out, const float* __restrict__ W1h,
                         const float* __restrict__ bh1) {
    __shared__ float red[256];
    const float* hf = out + (size_t)OFF_EMB + (size_t)NNODE*HID;
    int n = blockIdx.x;
    int t = threadIdx.x;
    if (n == 0) {
        if (t < 256) { g_hf[t] = hf[t]; g_hf[t + 256] = hf[t + 256]; }
    }
    float s = 0.f;
    for (int k = t; k < HID; k += 256)
        s += hf[k] * W1h[(size_t)k*512 + n];
    red[t] = s;
    __syncthreads();
    for (int st = 128; st; st >>= 1) {
        if (t < st) red[t] += red[t + st];
        __syncthreads();
    }
    if (t == 0) g_cvec[n] = red[0] + bh1[n];
}

// ----------------------------- launch 6: build Bm + split → gB1 ---------------
__global__ void k_buildsplit(const float* __restrict__ W1h) {
    int n = blockIdx.x;            // 0..511
    for (int k = threadIdx.x; k < 1024; k += blockDim.x) {
        float v = W1h[(size_t)(512 + k)*512 + n];
        if (k < 512) v += g_hf[k] * W1h[(size_t)(1536 + k)*512 + n];
        __nv_bfloat16 h, l; split_bf(v, h, l);
        gB1_hi[(size_t)n*1024 + k] = h;
        gB1_lo[(size_t)n*1024 + k] = l;
    }
}

// ----------------------------- launch 7: ef + X split -------------------------
__global__ void k_xef(float* __restrict__ out, const int* __restrict__ bch,
                      const float* __restrict__ tval, const float* __restrict__ isroot) {
    int u = blockIdx.x;
    int bc = bch[u];
    const float* ht = out + (size_t)OFF_EMB + (size_t)bc*512;
    float* ef = out + (size_t)OFF_EF + (size_t)u*2050;
    for (int j = threadIdx.x; j < 512; j += blockDim.x) {
        float h = ht[j], f = g_hf[j];
        float ab = fabsf(f - h), pr = f*h;
        ef[j] = f; ef[512 + j] = h; ef[1024 + j] = ab; ef[1536 + j] = pr;
        __nv_bfloat16 hh, hl, ah, al;
        split_bf(h, hh, hl); split_bf(ab, ah, al);
        gA_hi[(size_t)u*1024 + j]       = hh;
        gA_lo[(size_t)u*1024 + j]       = hl;
        gA_hi[(size_t)u*1024 + 512 + j] = ah;
        gA_lo[(size_t)u*1024 + 512 + j] = al;
    }
    if (threadIdx.x == 0) { ef[2048] = tval[u]; ef[2049] = isroot[u]; }
}

// ----------------------------- softmax ---------------------------------------
__global__ void k_softmax(float* __restrict__ out) {
    __shared__ float red[1024];
    int tid = threadIdx.x;
    float m = -1e30f;
    for (int i = tid; i < NNODE; i += 1024) m = fmaxf(m, out[i]);
    red[tid] = m; __syncthreads();
    for (int s = 512; s; s >>= 1) {
        if (tid < s) red[tid] = fmaxf(red[tid], red[tid + s]);
        __syncthreads();
    }
    float M = red[0]; __syncthreads();
    float sum = 0.f;
    for (int i = tid; i < NNODE; i += 1024) sum += __expf(out[i] - M);
    red[tid] = sum; __syncthreads();
    for (int s = 512; s; s >>= 1) {
        if (tid < s) red[tid] += red[tid + s];
        __syncthreads();
    }
    float inv = 1.f / red[0];
    for (int i = tid; i < NNODE; i += 1024)
        out[NNODE + i] = __expf(out[i] - M) * inv;
}

// ----------------------------- launcher --------------------------------------
extern "C" void kernel_launch(void* const* d_in, const int* in_sizes, int n_in,
                              void* d_out, int out_size) {
    const int*   ns     = (const int*)d_in[0];
    const int*   ch0    = (const int*)d_in[1];
    const int*   ch1    = (const int*)d_in[2];
    const int*   parent = (const int*)d_in[3];
    const int*   neigh  = (const int*)d_in[4];
    const int*   bch    = (const int*)d_in[5];
    const int*   focal  = (const int*)d_in[6];
    const float* tv     = (const float*)d_in[7];
    const float* isroot = (const float*)d_in[8];
    const float* W1     = (const float*)d_in[9];
    const float* b1     = (const float*)d_in[10];
    const float* W2     = (const float*)d_in[11];
    const float* b2     = (const float*)d_in[12];
    const float* Wh1    = (const float*)d_in[13];
    const float* bh1    = (const float*)d_in[14];
    const float* Wh2    = (const float*)d_in[15];
    const float* bh2    = (const float*)d_in[16];
    const float* Wh3    = (const float*)d_in[17];
    const float* bh3    = (const float*)d_in[18];
    float* out = (float*)d_out;

    dim3 gm(4, 64);
    k_prep<<<5121, 256>>>(W2, Wh2, ns, focal, W1, bh3, out);   // 1
    k_tree<<<512, 256>>>(ch0, ch1, parent, neigh, b1);         // 2 (tree + agg0)
    k_agg<<<NROW, 128>>>(neigh);                               // 3 (agg1 + split)
    // 4 (profiled slot): GEMM0
    k_mma<<<gm, 256>>>(0, NROW, 512, b2,
                       nullptr, nullptr, nullptr, nullptr, out + OFF_EMB);
    k_hfcvec<<<512, 256>>>(out, Wh1, bh1);                     // 5
    k_buildsplit<<<512, 256>>>(Wh1);                           // 6
    k_xef<<<NNODE, 256>>>(out, bch, tv, isroot);               // 7
    // 8: GEMM1
    k_mma<<<gm, 256>>>(1, NNODE, 1024, nullptr,
                       Wh1 + (size_t)2048*512, Wh1 + (size_t)2049*512,
                       tv, isroot, nullptr);
    // 9: GEMM2 + fused logits
    k_mma<<<gm, 256>>>(2, NNODE, 512, bh2,
                       Wh3, nullptr, nullptr, nullptr, out);
    k_softmax<<<1, 1024>>>(out);                               // 10
}

// round 13
// speedup vs baseline: 1.0534x; 1.0534x over previous
#include <cuda_runtime.h>
#include <cuda_bf16.h>
#include <cstdint>

#define NLEAF 4096
#define NNODE 8191
#define NROW  8192
#define HID   512

#define OFF_EF     16382
#define OFF_EMB    16807932
#define OFF_FOCAL  21002236

// ----------------------------- scratch ---------------------------------------
__device__ float g_dW[NROW*HID];
__device__ float g_h[NROW*HID];
__device__ float g_cvec[HID];
__device__ float g_hf[HID];
__device__ float g_c[NNODE];          // leaves stay 0 forever
__device__ int   g_postF[NNODE];
__device__ int   g_preF[NNODE];

// bf16 split operand buffers (k-contiguous)
__device__ __nv_bfloat16 gA_hi[(size_t)NROW*1024];
__device__ __nv_bfloat16 gA_lo[(size_t)NROW*1024];
__device__ __nv_bfloat16 gZ_hi[(size_t)NROW*512];
__device__ __nv_bfloat16 gZ_lo[(size_t)NROW*512];
__device__ __nv_bfloat16 gB0_hi[(size_t)512*1024];   // W2   [n][k]
__device__ __nv_bfloat16 gB0_lo[(size_t)512*1024];
__device__ __nv_bfloat16 gB1_hi[(size_t)512*1024];   // Bm   [n][k]
__device__ __nv_bfloat16 gB1_lo[(size_t)512*1024];
__device__ __nv_bfloat16 gB2_hi[(size_t)512*1024];   // Wh2  [n][k]
__device__ __nv_bfloat16 gB2_lo[(size_t)512*1024];

// ----------------------------- helpers ----------------------------------------
__device__ __forceinline__ void st_rel(int* p, int v) {
    asm volatile("st.release.gpu.global.b32 [%0], %1;" :: "l"(p), "r"(v) : "memory");
}
__device__ __forceinline__ int ld_acq(const int* p) {
    int v;
    asm volatile("ld.acquire.gpu.global.b32 %0, [%1];" : "=r"(v) : "l"(p) : "memory");
    return v;
}
__device__ __forceinline__ void split_bf(float v, __nv_bfloat16 &h, __nv_bfloat16 &l) {
    h = __float2bfloat16(v);
    l = __float2bfloat16(v - __bfloat162float(h));
}
__device__ __forceinline__ float eluf(float x) { return x > 0.f ? x : expm1f(x); }

__device__ __forceinline__ void mma_bf16(float* d, const uint32_t* a, uint32_t b0, uint32_t b1) {
    asm volatile(
        "mma.sync.aligned.m16n8k16.row.col.f32.bf16.bf16.f32 "
        "{%0,%1,%2,%3}, {%4,%5,%6,%7}, {%8,%9}, {%0,%1,%2,%3};"
        : "+f"(d[0]), "+f"(d[1]), "+f"(d[2]), "+f"(d[3])
        : "r"(a[0]), "r"(a[1]), "r"(a[2]), "r"(a[3]), "r"(b0), "r"(b1));
}
__device__ __forceinline__ void ldm_x4(uint32_t* r, uint32_t saddr) {
    asm volatile("ldmatrix.sync.aligned.m8n8.x4.shared.b16 {%0,%1,%2,%3}, [%4];"
        : "=r"(r[0]), "=r"(r[1]), "=r"(r[2]), "=r"(r[3]) : "r"(saddr));
}

// ----------------------------- launch 1: prep ---------------------------------
__global__ void k_prep(const float* __restrict__ W2, const float* __restrict__ Wh2,
                       const int* __restrict__ ns, const int* __restrict__ focal,
                       const float* __restrict__ W1, const float* __restrict__ bh3,
                       float* __restrict__ out) {
    int b = blockIdx.x;
    if (b < 1024) {
        if (b < 64) {
            int i = b*256 + threadIdx.x;    // covers 16384 >= 2*NNODE
            if (i < NNODE) { g_postF[i] = 0; out[i] = bh3[0]; }
            else if (i < 2*NNODE) g_preF[i - NNODE] = 0;
        }
        const float* W = (b < 512) ? W2 : Wh2;
        __nv_bfloat16* bh = (b < 512) ? gB0_hi : gB2_hi;
        __nv_bfloat16* bl = (b < 512) ? gB0_lo : gB2_lo;
        int n = b & 511;
        for (int k = threadIdx.x; k < 512; k += blockDim.x) {
            float v = W[(size_t)k*512 + n];
            __nv_bfloat16 h, l; split_bf(v, h, l);
            bh[(size_t)n*1024 + k] = h;
            bl[(size_t)n*1024 + k] = l;
        }
        return;
    }
    int bb = b - 1024;                      // 0..4096
    int u, src;
    if (bb == NLEAF) { u = NNODE; src = focal[0]; }
    else {
        u = bb; src = ns[bb];
        if (threadIdx.x == 0) out[OFF_FOCAL + bb] = (bb == focal[0]) ? 1.f : 0.f;
        if (src < 0) return;
    }
    if (threadIdx.x < 128) {
        const float4* w = (const float4*)(W1 + (size_t)src*HID);
        float4* d = (float4*)(g_dW + (size_t)u*HID);
        d[threadIdx.x] = w[threadIdx.x];
    }
}

// ----------------------------- launch 2: tree + agg phase 0 -------------------
__global__ void k_tree(const int* __restrict__ ch0, const int* __restrict__ ch1,
                       const int* __restrict__ parent, const int* __restrict__ neigh,
                       const float* __restrict__ bias) {
    const int w    = blockIdx.x * (blockDim.x >> 5) + (threadIdx.x >> 5);
    const int lane = threadIdx.x & 31;
    const int NI   = NNODE - NLEAF;
    const int root = NNODE - 1;

    if (w < NI) {
        const int u = NLEAF + w;
        const int a = ch0[u], b = ch1[u];

        if (a >= NLEAF) while (!ld_acq(&g_postF[a])) { }
        if (b >= NLEAF) while (!ld_acq(&g_postF[b])) { }
        __syncwarp();
        float ca = __ldcg(&g_c[a]);
        float cb = __ldcg(&g_c[b]);
        float cu = 1.f / (3.f - ca - cb);
        const float4* pa = (const float4*)(g_dW + (size_t)a*HID);
        const float4* pb = (const float4*)(g_dW + (size_t)b*HID);
        float4*       pu = (float4*)(g_dW + (size_t)u*HID);
        #pragma unroll
        for (int j = 0; j < 4; j++) {
            int c4 = lane + j*32;
            float4 x = __ldcg(pa + c4), y = __ldcg(pb + c4), r;
            r.x = cu*(x.x+y.x); r.y = cu*(x.y+y.y);
            r.z = cu*(x.z+y.z); r.w = cu*(x.w+y.w);
            pu[c4] = r;
        }
        if (lane == 0) g_c[u] = cu;
        __threadfence();
        __syncwarp();
        if (lane == 0) {
            st_rel(&g_postF[u], 1);
            if (u == root) st_rel(&g_preF[u], 1);
        }
        __syncwarp();

        if (u != root) {
            const int p = parent[u];
            while (!ld_acq(&g_preF[p])) { }
            __syncwarp();
            const float4* pp = (const float4*)(g_dW + (size_t)p*HID);
            #pragma unroll
            for (int j = 0; j < 4; j++) {
                int c4 = lane + j*32;
                float4 x = __ldcg(pp + c4);
                float4 r = pu[c4];
                r.x += cu*x.x; r.y += cu*x.y; r.z += cu*x.z; r.w += cu*x.w;
                pu[c4] = r;
            }
            __threadfence();
            __syncwarp();
            if (lane == 0) st_rel(&g_preF[u], 1);
            __syncwarp();
        }
    }

    // ---- agg phase 0: rows 2w, 2w+1 ----
    #pragma unroll
    for (int q = 0; q < 2; q++) {
        int rrow = 2*w + q;                 // 0..8191
        int n0 = neigh[3*rrow], n1 = neigh[3*rrow+1], n2 = neigh[3*rrow+2];
        if (lane == 0) {
            if (rrow >= NLEAF && rrow < NNODE) while (!ld_acq(&g_preF[rrow])) { }
            if (n0 >= NLEAF && n0 < NNODE)     while (!ld_acq(&g_preF[n0])) { }
            if (n1 >= NLEAF && n1 < NNODE)     while (!ld_acq(&g_preF[n1])) { }
            if (n2 >= NLEAF && n2 < NNODE)     while (!ld_acq(&g_preF[n2])) { }
        }
        __syncwarp();
        float inv = 1.f / (1.f + (n0 >= 0) + (n1 >= 0) + (n2 >= 0));
        const float4* s  = (const float4*)(g_dW + (size_t)rrow*HID);
        const float4* p0 = (const float4*)(g_dW + (size_t)(n0 >= 0 ? n0 : 0)*HID);
        const float4* p1 = (const float4*)(g_dW + (size_t)(n1 >= 0 ? n1 : 0)*HID);
        const float4* p2 = (const float4*)(g_dW + (size_t)(n2 >= 0 ? n2 : 0)*HID);
        float4* dst = (float4*)(g_h + (size_t)rrow*HID);
        const float4* bb4 = (const float4*)bias;
        #pragma unroll
        for (int j4 = 0; j4 < 4; j4++) {
            int j = lane + j4*32;
            float4 v = __ldcg(s + j);
            if (n0 >= 0) { float4 t = __ldcg(p0 + j); v.x += t.x; v.y += t.y; v.z += t.z; v.w += t.w; }
            if (n1 >= 0) { float4 t = __ldcg(p1 + j); v.x += t.x; v.y += t.y; v.z += t.z; v.w += t.w; }
            if (n2 >= 0) { float4 t = __ldcg(p2 + j); v.x += t.x; v.y += t.y; v.z += t.z; v.w += t.w; }
            float4 bv = bb4[j];
            v.x = fmaxf(v.x*inv + bv.x, 0.f); v.y = fmaxf(v.y*inv + bv.y, 0.f);
            v.z = fmaxf(v.z*inv + bv.z, 0.f); v.w = fmaxf(v.w*inv + bv.w, 0.f);
            dst[j] = v;
        }
    }
}

// ----------------------------- launch 3: agg phase 1 + split ------------------
__global__ void k_agg(const int* __restrict__ neigh) {
    int u = blockIdx.x;
    int n0 = neigh[3*u], n1 = neigh[3*u+1], n2 = neigh[3*u+2];
    float inv = 1.f / (1.f + (n0 >= 0) + (n1 >= 0) + (n2 >= 0));
    const float4* s  = (const float4*)(g_h + (size_t)u*HID);
    const float4* p0 = (const float4*)(g_h + (size_t)(n0 >= 0 ? n0 : 0)*HID);
    const float4* p1 = (const float4*)(g_h + (size_t)(n1 >= 0 ? n1 : 0)*HID);
    const float4* p2 = (const float4*)(g_h + (size_t)(n2 >= 0 ? n2 : 0)*HID);
    int j = threadIdx.x;
    float4 v = s[j];
    if (n0 >= 0) { float4 t = p0[j]; v.x += t.x; v.y += t.y; v.z += t.z; v.w += t.w; }
    if (n1 >= 0) { float4 t = p1[j]; v.x += t.x; v.y += t.y; v.z += t.z; v.w += t.w; }
    if (n2 >= 0) { float4 t = p2[j]; v.x += t.x; v.y += t.y; v.z += t.z; v.w += t.w; }
    v.x *= inv; v.y *= inv; v.z *= inv; v.w *= inv;
    __nv_bfloat16 h0,l0,h1,l1,h2,l2,h3,l3;
    split_bf(v.x, h0, l0); split_bf(v.y, h1, l1);
    split_bf(v.z, h2, l2); split_bf(v.w, h3, l3);
    ushort4 sh = { __bfloat16_as_ushort(h0), __bfloat16_as_ushort(h1),
                   __bfloat16_as_ushort(h2), __bfloat16_as_ushort(h3) };
    ushort4 sl = { __bfloat16_as_ushort(l0), __bfloat16_as_ushort(l1),
                   __bfloat16_as_ushort(l2), __bfloat16_as_ushort(l3) };
    *(ushort4*)(gA_hi + (size_t)u*1024 + 4*j) = sh;
    *(ushort4*)(gA_lo + (size_t)u*1024 + 4*j) = sl;
}

// ----------------------------- mma.sync bf16x3 GEMM (ldmatrix) ----------------
// mode 0: A=gA (stride 1024), B=gB0, K=512 ; Cout = D + bias (fp32)
// mode 1: A=gA (stride 1024), B=gB1, K=1024; gZ = split(elu(D + cvec + t*wt + r*wr))
// mode 2: A=gZ (stride 512),  B=gB2, K=512 ; z=elu(D+bias); atomicAdd(out[m], z*W3[n]) (wt=W3)
#define SROW 40   // smem row stride in bf16 (80B) -> ldmatrix conflict-free
__global__ __launch_bounds__(256, 2) void k_mma(
        int mode, int M, int K,
        const float* __restrict__ bias,
        const float* __restrict__ wt, const float* __restrict__ wr,
        const float* __restrict__ tv, const float* __restrict__ rv,
        float* __restrict__ Cout) {
    const __nv_bfloat16* Ahi = (mode == 2) ? gZ_hi : gA_hi;
    const __nv_bfloat16* Alo = (mode == 2) ? gZ_lo : gA_lo;
    const __nv_bfloat16* Bhi = (mode == 0) ? gB0_hi : (mode == 1 ? gB1_hi : gB2_hi);
    const __nv_bfloat16* Blo = (mode == 0) ? gB0_lo : (mode == 1 ? gB1_lo : gB2_lo);
    const int strideA = (mode == 2) ? 512 : 1024;

    __shared__ __align__(16) __nv_bfloat16 sm[4*128*SROW];   // 40960 B: Ah, Al, Bh, Bl
    const int tid  = threadIdx.x;
    const int wid  = tid >> 5;
    const int lane = tid & 31;
    const int gid  = lane >> 2;       // 0..7  (epilogue row-in-group)
    const int tig  = lane & 3;        // 0..3  (epilogue col pair)
    const int m0 = blockIdx.y * 128;
    const int n0 = blockIdx.x * 128;
    const int wm = (wid & 3) * 32;    // warp m offset
    const int wn = (wid >> 2) * 64;   // warp n offset
    const int Cn = K >> 5;            // 32-wide K chunks

    // ldmatrix addressing (per-thread, hoisted)
    const uint32_t sbase = (uint32_t)__cvta_generic_to_shared(sm);
    const int am  = lane >> 3;        // matrix id 0..3
    const int ar  = lane & 7;         // row within matrix
    const int rA  = wm + (am & 1)*8 + ar;    // + i*16 ; col += (am>>1)*8
    const int cA  = (am >> 1)*8;
    const int rB  = wn + (am >> 1)*8 + ar;   // + jp*16 ; col += (am&1)*8
    const int cB  = (am & 1)*8;
    const uint32_t offAh = sbase;
    const uint32_t offAl = sbase + 1u*128*SROW*2;
    const uint32_t offBh = sbase + 2u*128*SROW*2;
    const uint32_t offBl = sbase + 3u*128*SROW*2;

    float acc[2][8][4];
    #pragma unroll
    for (int i = 0; i < 2; i++)
        #pragma unroll
        for (int j = 0; j < 8; j++)
            #pragma unroll
            for (int q = 0; q < 4; q++) acc[i][j][q] = 0.f;

    uint4 rAh[2], rAl[2], rBh[2], rBl[2];
    auto load_g = [&](int c) {
        const size_t kb = (size_t)c * 32;
        #pragma unroll
        for (int it = 0; it < 2; it++) {
            int idx = it*256 + tid;
            int row = idx >> 2, seg = idx & 3;
            rAh[it] = *(const uint4*)(Ahi + (size_t)(m0+row)*strideA + kb + seg*8);
            rAl[it] = *(const uint4*)(Alo + (size_t)(m0+row)*strideA + kb + seg*8);
            rBh[it] = *(const uint4*)(Bhi + (size_t)(n0+row)*1024 + kb + seg*8);
            rBl[it] = *(const uint4*)(Blo + (size_t)(n0+row)*1024 + kb + seg*8);
        }
    };
    auto store_s = [&]() {
        #pragma unroll
        for (int it = 0; it < 2; it++) {
            int idx = it*256 + tid;
            int row = idx >> 2, seg = idx & 3;
            int so = row*SROW + seg*8;
            *(uint4*)(sm + 0*128*SROW + so) = rAh[it];
            *(uint4*)(sm + 1*128*SROW + so) = rAl[it];
            *(uint4*)(sm + 2*128*SROW + so) = rBh[it];
            *(uint4*)(sm + 3*128*SROW + so) = rBl[it];
        }
    };

    load_g(0);
    for (int c = 0; c < Cn; c++) {
        store_s();
        __syncthreads();
        if (c + 1 < Cn) load_g(c + 1);     // global->reg prefetch overlaps compute
        #pragma unroll
        for (int ks = 0; ks < 32; ks += 16) {
            uint32_t aH[2][4], aL[2][4];
            #pragma unroll
            for (int i = 0; i < 2; i++) {
                uint32_t adr = (uint32_t)(((rA + i*16)*SROW + ks + cA) * 2);
                ldm_x4(aH[i], offAh + adr);
                ldm_x4(aL[i], offAl + adr);
            }
            #pragma unroll
            for (int jp = 0; jp < 4; jp++) {
                uint32_t bh[4], bl[4];
                uint32_t adr = (uint32_t)(((rB + jp*16)*SROW + ks + cB) * 2);
                ldm_x4(bh, offBh + adr);
                ldm_x4(bl, offBl + adr);
                #pragma unroll
                for (int i = 0; i < 2; i++) {
                    mma_bf16(acc[i][2*jp],   aH[i], bh[0], bh[1]);
                    mma_bf16(acc[i][2*jp],   aH[i], bl[0], bl[1]);
                    mma_bf16(acc[i][2*jp],   aL[i], bh[0], bh[1]);
                    mma_bf16(acc[i][2*jp+1], aH[i], bh[2], bh[3]);
                    mma_bf16(acc[i][2*jp+1], aH[i], bl[2], bl[3]);
                    mma_bf16(acc[i][2*jp+1], aL[i], bh[2], bh[3]);
                }
            }
        }
        __syncthreads();
    }

    // ----- epilogue -----
    #pragma unroll
    for (int i = 0; i < 2; i++) {
        #pragma unroll
        for (int r2 = 0; r2 < 2; r2++) {
            int m = m0 + wm + i*16 + gid + r2*8;
            if (m >= M) continue;
            float t = 0.f, r = 0.f;
            if (mode == 1) { t = tv[m]; r = rv[m]; }
            float part = 0.f;                 // mode 2: logits partial
            #pragma unroll
            for (int j = 0; j < 8; j++) {
                int n = n0 + wn + j*8 + tig*2;
                float v0 = acc[i][j][r2*2 + 0];
                float v1 = acc[i][j][r2*2 + 1];
                if (mode == 0) {
                    float2 bv = *(const float2*)&bias[n];
                    *(float2*)(Cout + (size_t)m*512 + n) = make_float2(v0 + bv.x, v1 + bv.y);
                } else if (mode == 1) {
                    float2 cv = *(const float2*)&g_cvec[n];
                    float2 wtv = *(const float2*)&wt[n];
                    float2 wrv = *(const float2*)&wr[n];
                    float z0 = eluf(v0 + cv.x + t*wtv.x + r*wrv.x);
                    float z1 = eluf(v1 + cv.y + t*wtv.y + r*wrv.y);
                    __nv_bfloat16 h0, l0, h1, l1;
                    split_bf(z0, h0, l0); split_bf(z1, h1, l1);
                    ushort2 sh = { __bfloat16_as_ushort(h0), __bfloat16_as_ushort(h1) };
                    ushort2 sl = { __bfloat16_as_ushort(l0), __bfloat16_as_ushort(l1) };
                    *(ushort2*)(gZ_hi + (size_t)m*512 + n) = sh;
                    *(ushort2*)(gZ_lo + (size_t)m*512 + n) = sl;
                } else {
                    float2 bv = *(const float2*)&bias[n];
                    float2 w3 = *(const float2*)&wt[n];     // wt = W_h3
                    part += eluf(v0 + bv.x)*w3.x + eluf(v1 + bv.y)*w3.y;
                }
            }
            if (mode == 2) {
                part += __shfl_xor_sync(0xffffffffu, part, 1);
                part += __shfl_xor_sync(0xffffffffu, part, 2);
                if (tig == 0) atomicAdd(&Cout[m], part);
            }
        }
    }
}

// ----------------------------- launch 5: hf + cvec (parallel) -----------------
__global__ void k_hfcvec(const float* __restrict__ out, const float* __restrict__ W1h,
                         const float* __restrict__ bh1) {
    __shared__ float red[256];
    const float* hf = out + (size_t)OFF_EMB + (size_t)NNODE*HID;
    int n = blockIdx.x;
    int t = threadIdx.x;
    if (n == 0) {
        if (t < 256) { g_hf[t] = hf[t]; g_hf[t + 256] = hf[t + 256]; }
    }
    float s = 0.f;
    for (int k = t; k < HID; k += 256)
        s += hf[k] * W1h[(size_t)k*512 + n];
    red[t] = s;
    __syncthreads();
    for (int st = 128; st; st >>= 1) {
        if (t < st) red[t] += red[t + st];
        __syncthreads();
    }
    if (t == 0) g_cvec[n] = red[0] + bh1[n];
}

// ----------------------------- launch 6: build Bm + split → gB1 ---------------
__global__ void k_buildsplit(const float* __restrict__ W1h) {
    int n = blockIdx.x;            // 0..511
    for (int k = threadIdx.x; k < 1024; k += blockDim.x) {
        float v = W1h[(size_t)(512 + k)*512 + n];
        if (k < 512) v += g_hf[k] * W1h[(size_t)(1536 + k)*512 + n];
        __nv_bfloat16 h, l; split_bf(v, h, l);
        gB1_hi[(size_t)n*1024 + k] = h;
        gB1_lo[(size_t)n*1024 + k] = l;
    }
}

// ----------------------------- launch 7: ef + X split -------------------------
__global__ void k_xef(float* __restrict__ out, const int* __restrict__ bch,
                      const float* __restrict__ tval, const float* __restrict__ isroot) {
    int u = blockIdx.x;
    int bc = bch[u];
    const float* ht = out + (size_t)OFF_EMB + (size_t)bc*512;
    float* ef = out + (size_t)OFF_EF + (size_t)u*2050;
    for (int j = threadIdx.x; j < 512; j += blockDim.x) {
        float h = ht[j], f = g_hf[j];
        float ab = fabsf(f - h), pr = f*h;
        ef[j] = f; ef[512 + j] = h; ef[1024 + j] = ab; ef[1536 + j] = pr;
        __nv_bfloat16 hh, hl, ah, al;
        split_bf(h, hh, hl); split_bf(ab, ah, al);
        gA_hi[(size_t)u*1024 + j]       = hh;
        gA_lo[(size_t)u*1024 + j]       = hl;
        gA_hi[(size_t)u*1024 + 512 + j] = ah;
        gA_lo[(size_t)u*1024 + 512 + j] = al;
    }
    if (threadIdx.x == 0) { ef[2048] = tval[u]; ef[2049] = isroot[u]; }
}

// ----------------------------- softmax ---------------------------------------
__global__ void k_softmax(float* __restrict__ out) {
    __shared__ float red[1024];
    int tid = threadIdx.x;
    float m = -1e30f;
    for (int i = tid; i < NNODE; i += 1024) m = fmaxf(m, out[i]);
    red[tid] = m; __syncthreads();
    for (int s = 512; s; s >>= 1) {
        if (tid < s) red[tid] = fmaxf(red[tid], red[tid + s]);
        __syncthreads();
    }
    float M = red[0]; __syncthreads();
    float sum = 0.f;
    for (int i = tid; i < NNODE; i += 1024) sum += __expf(out[i] - M);
    red[tid] = sum; __syncthreads();
    for (int s = 512; s; s >>= 1) {
        if (tid < s) red[tid] += red[tid + s];
        __syncthreads();
    }
    float inv = 1.f / red[0];
    for (int i = tid; i < NNODE; i += 1024)
        out[NNODE + i] = __expf(out[i] - M) * inv;
}

// ----------------------------- launcher --------------------------------------
extern "C" void kernel_launch(void* const* d_in, const int* in_sizes, int n_in,
                              void* d_out, int out_size) {
    const int*   ns     = (const int*)d_in[0];
    const int*   ch0    = (const int*)d_in[1];
    const int*   ch1    = (const int*)d_in[2];
    const int*   parent = (const int*)d_in[3];
    const int*   neigh  = (const int*)d_in[4];
    const int*   bch    = (const int*)d_in[5];
    const int*   focal  = (const int*)d_in[6];
    const float* tv     = (const float*)d_in[7];
    const float* isroot = (const float*)d_in[8];
    const float* W1     = (const float*)d_in[9];
    const float* b1     = (const float*)d_in[10];
    const float* W2     = (const float*)d_in[11];
    const float* b2     = (const float*)d_in[12];
    const float* Wh1    = (const float*)d_in[13];
    const float* bh1    = (const float*)d_in[14];
    const float* Wh2    = (const float*)d_in[15];
    const float* bh2    = (const float*)d_in[16];
    const float* Wh3    = (const float*)d_in[17];
    const float* bh3    = (const float*)d_in[18];
    float* out = (float*)d_out;

    dim3 gm(4, 64);
    k_prep<<<5121, 256>>>(W2, Wh2, ns, focal, W1, bh3, out);   // 1
    k_tree<<<512, 256>>>(ch0, ch1, parent, neigh, b1);         // 2 (tree + agg0)
    k_agg<<<NROW, 128>>>(neigh);                               // 3 (agg1 + split)
    // 4 (profiled slot): GEMM0
    k_mma<<<gm, 256>>>(0, NROW, 512, b2,
                       nullptr, nullptr, nullptr, nullptr, out + OFF_EMB);
    k_hfcvec<<<512, 256>>>(out, Wh1, bh1);                     // 5
    k_buildsplit<<<512, 256>>>(Wh1);                           // 6
    k_xef<<<NNODE, 256>>>(out, bch, tv, isroot);               // 7
    // 8: GEMM1
    k_mma<<<gm, 256>>>(1, NNODE, 1024, nullptr,
                       Wh1 + (size_t)2048*512, Wh1 + (size_t)2049*512,
                       tv, isroot, nullptr);
    // 9: GEMM2 + fused logits
    k_mma<<<gm, 256>>>(2, NNODE, 512, bh2,
                       Wh3, nullptr, nullptr, nullptr, out);
    k_softmax<<<1, 1024>>>(out);                               // 10
}